// round 14
// baseline (speedup 1.0000x reference)
#include <cuda_runtime.h>
#include <cuda_bf16.h>
#include <math.h>
#include <stdint.h>

// Problem constants
#define B_ 2
#define T_ 2048
#define C_ 1024
#define H_ 16
#define ROWS_ (B_*T_)            // 4096
#define ELEMS_ (ROWS_*C_)        // 4194304
#define NPROW_ (ROWS_/2)         // 2048 pair-rows
#define NP_ (T_/2)               // 1024 pairs per batch

// packed per-(pair,head) scan operand block
#define PACKB_ 2560
#define PSTR_  ((size_t)H_ * PACKB_)   // stride between consecutive pairs

// ---------------- scratch (device globals; no cudaMalloc allowed) ----------
__device__ float g_q  [ELEMS_];
__device__ float g_k  [ELEMS_];
__device__ float g_v  [ELEMS_];
__device__ float g_vf [ELEMS_];
__device__ float g_deltas[(size_t)ROWS_*4*C_];   // [4096, 4096]
__device__ float g_gate[ELEMS_];
__device__ float g_yscan[ELEMS_];
__device__ __nv_bfloat16 g_sv[ELEMS_];
__device__ char  g_pack[(size_t)NPROW_*H_*PACKB_];   // ~84 MB

// bf16 hi/lo operand buffers for bf16x3 GEMMs
__device__ __nv_bfloat16 g_xqh[ELEMS_], g_xql[ELEMS_];
__device__ __nv_bfloat16 g_xkh[ELEMS_], g_xkl[ELEMS_];
__device__ __nv_bfloat16 g_xvh[ELEMS_], g_xvl[ELEMS_];
__device__ __nv_bfloat16 g_x0h[ELEMS_], g_x0l[ELEMS_];
__device__ __nv_bfloat16 g_wqh[C_*C_],  g_wql[C_*C_];
__device__ __nv_bfloat16 g_wkh[C_*C_],  g_wkl[C_*C_];
__device__ __nv_bfloat16 g_wvh[C_*C_],  g_wvl[C_*C_];
__device__ __nv_bfloat16 g_wph[C_*C_],  g_wpl[C_*C_];
__device__ __nv_bfloat16 g_xh [ROWS_*128], g_xl [ROWS_*128];
__device__ __nv_bfloat16 g_mth[4*C_*128],  g_mtl[4*C_*128];
__device__ __nv_bfloat16 g_yfh[ELEMS_], g_yfl[ELEMS_];

// ---------------- helpers ----------------------------------------------------
__device__ __forceinline__ uint32_t smem_u32(const void* p) {
    uint32_t a;
    asm("{ .reg .u64 t; cvta.to.shared.u64 t, %1; cvt.u32.u64 %0, t; }"
        : "=r"(a) : "l"(p));
    return a;
}
#define CPA16(dst32, src) \
    asm volatile("cp.async.cg.shared.global [%0], [%1], 16;" \
                 :: "r"(dst32), "l"(src))
#define CPA_COMMIT() asm volatile("cp.async.commit_group;" ::: "memory")
#define CPA_WAIT(n)  asm volatile("cp.async.wait_group %0;" :: "n"(n) : "memory")

#define LDSM_X4(r0, r1, r2, r3, addr) \
    asm volatile("ldmatrix.sync.aligned.m8n8.x4.shared.b16 {%0,%1,%2,%3}, [%4];" \
                 : "=r"(r0), "=r"(r1), "=r"(r2), "=r"(r3) : "r"(addr))

__device__ __forceinline__ float4 lds128f(uint32_t a) {
    float4 v;
    asm volatile("ld.shared.v4.f32 {%0,%1,%2,%3}, [%4];"
                 : "=f"(v.x), "=f"(v.y), "=f"(v.z), "=f"(v.w) : "r"(a));
    return v;
}
__device__ __forceinline__ uint4 lds128u(uint32_t a) {
    uint4 v;
    asm volatile("ld.shared.v4.u32 {%0,%1,%2,%3}, [%4];"
                 : "=r"(v.x), "=r"(v.y), "=r"(v.z), "=r"(v.w) : "r"(a));
    return v;
}
__device__ __forceinline__ float ldsf32(uint32_t a) {
    float v;
    asm volatile("ld.shared.f32 %0, [%1];" : "=f"(v) : "r"(a));
    return v;
}
__device__ __forceinline__ float ldsbf16(uint32_t a) {
    unsigned short v;
    asm volatile("ld.shared.u16 %0, [%1];" : "=h"(v) : "r"(a));
    __nv_bfloat16 b = *reinterpret_cast<__nv_bfloat16*>(&v);
    return __bfloat162float(b);
}

__device__ __forceinline__ void mma_bf16(float* c, const uint32_t* a,
                                         uint32_t b0, uint32_t b1) {
    asm volatile(
        "mma.sync.aligned.m16n8k16.row.col.f32.bf16.bf16.f32 "
        "{%0,%1,%2,%3}, {%4,%5,%6,%7}, {%8,%9}, {%0,%1,%2,%3};"
        : "+f"(c[0]), "+f"(c[1]), "+f"(c[2]), "+f"(c[3])
        : "r"(a[0]), "r"(a[1]), "r"(a[2]), "r"(a[3]), "r"(b0), "r"(b1));
}

__device__ __forceinline__ void f2hl(float v, __nv_bfloat16& h, __nv_bfloat16& l) {
    h = __float2bfloat16(v);
    l = __float2bfloat16(v - __bfloat162float(h));
}
__device__ __forceinline__ float2 bf2(uint32_t u) {
    return __bfloat1622float2(*(const __nv_bfloat162*)&u);
}

// ---------------- conversion kernels ----------------------------------------
__global__ void conv_w4(const float* __restrict__ Wq, const float* __restrict__ Wk,
                        const float* __restrict__ Wv, const float* __restrict__ Wp)
{
    int i = blockIdx.x * blockDim.x + threadIdx.x;
    int sel = i >> 20;
    int j = i & (C_ * C_ - 1);
    switch (sel) {
        case 0: f2hl(Wq[j], g_wqh[j], g_wql[j]); break;
        case 1: f2hl(Wk[j], g_wkh[j], g_wkl[j]); break;
        case 2: f2hl(Wv[j], g_wvh[j], g_wvl[j]); break;
        default: f2hl(Wp[j], g_wph[j], g_wpl[j]); break;
    }
}

__global__ void conv_xmt(const float* __restrict__ x, const float* __restrict__ miss)
{
    int i = blockIdx.x * blockDim.x + threadIdx.x;
    if (i < ROWS_ * 128) {
        int row = i >> 7, c = i & 127;
        f2hl(x[(size_t)row * C_ + c], g_xh[i], g_xl[i]);
    } else {
        int j = i - ROWS_ * 128;
        int nrow = j >> 7, k = j & 127;
        f2hl(miss[(size_t)k * (4 * C_) + nrow], g_mth[j], g_mtl[j]);
    }
}

// ---------------- kernel 1: token shift + mixes (emit bf16 hi/lo) ----------
__global__ void prep_kernel(const float* __restrict__ x,
                            const float* __restrict__ x0,
                            const float* __restrict__ dx0,
                            const float* __restrict__ mq,
                            const float* __restrict__ mk,
                            const float* __restrict__ mv)
{
    int idx = blockIdx.x * blockDim.x + threadIdx.x;
    if (idx >= ELEMS_) return;
    int c   = idx & (C_ - 1);
    int row = idx >> 10;
    int t   = row & (T_ - 1);
    float xc = x[idx];
    float xp = (t == 0) ? 0.f : x[idx - C_];
    float dx = xp - xc;
    f2hl(xc + dx * mq[c],            g_xqh[idx], g_xql[idx]);
    f2hl(xc + dx * mk[c],            g_xkh[idx], g_xkl[idx]);
    f2hl(xc + dx * mv[c],            g_xvh[idx], g_xvl[idx]);
    f2hl(x0[idx] + dx0[idx] * mv[c], g_x0h[idx], g_x0l[idx]);
}

// ---------------- GEMM core: mma.sync bf16x3, 128x64 tile, 2 CTAs/SM --------
#define GSTAGE_ (49152)
#define GSMEM_BYTES (2 * GSTAGE_)

template<bool EPI>
__device__ __forceinline__
void gemm_core(const __nv_bfloat16* __restrict__ Ah, const __nv_bfloat16* __restrict__ Al,
               const __nv_bfloat16* __restrict__ Bh, const __nv_bfloat16* __restrict__ Bl,
               const float* __restrict__ Res, float* __restrict__ Cout,
               int Nn, int K, uint32_t smem32)
{
    const int tid  = threadIdx.x;
    const int wid  = tid >> 5;
    const int lane = tid & 31;
    const int wm   = wid >> 1;
    const int wn   = wid & 1;
    const int bm   = blockIdx.y * 128;
    const int bn   = blockIdx.x * 64;
    const int NC   = K >> 6;

    const int lrow = ((lane >> 3) & 1) * 8 + (lane & 7);
    const int lkof = (lane >> 4);

    auto issue = [&](int ck, int s) {
        const int kcol = ck * 64;
        const uint32_t sb = smem32 + (uint32_t)s * GSTAGE_;
#pragma unroll
        for (int t = 0; t < 2; t++) {
            const __nv_bfloat16* gp = t ? Al : Ah;
#pragma unroll
            for (int i = 0; i < 4; i++) {
                int id  = tid + i * 256;
                int row = id >> 3;
                int j   = id & 7;
                uint32_t dst = sb + (uint32_t)t * 16384 + row * 128
                             + ((uint32_t)(j ^ (row & 7)) << 4);
                const void* src = gp + (size_t)(bm + row) * K + kcol + j * 8;
                CPA16(dst, src);
            }
        }
#pragma unroll
        for (int t = 0; t < 2; t++) {
            const __nv_bfloat16* gp = t ? Bl : Bh;
#pragma unroll
            for (int i = 0; i < 2; i++) {
                int id  = tid + i * 256;
                int row = id >> 3;
                int j   = id & 7;
                uint32_t dst = sb + 32768u + (uint32_t)t * 8192 + row * 128
                             + ((uint32_t)(j ^ (row & 7)) << 4);
                const void* src = gp + (size_t)(bn + row) * K + kcol + j * 8;
                CPA16(dst, src);
            }
        }
        CPA_COMMIT();
    };

    float acc[2][4][4];
#pragma unroll
    for (int mt = 0; mt < 2; mt++)
#pragma unroll
        for (int nt = 0; nt < 4; nt++)
#pragma unroll
            for (int r = 0; r < 4; r++) acc[mt][nt][r] = 0.f;

    issue(0, 0);
    if (NC > 1) issue(1, 1);

    for (int ck = 0; ck < NC; ck++) {
        if (ck + 1 < NC) { CPA_WAIT(1); } else { CPA_WAIT(0); }
        __syncthreads();

        const uint32_t sb = smem32 + (uint32_t)(ck & 1) * GSTAGE_;

#pragma unroll
        for (int ks = 0; ks < 4; ks++) {
            auto addr16 = [&](uint32_t tbase, int row16) -> uint32_t {
                int row = row16 + lrow;
                int j   = ks * 2 + lkof;
                return tbase + row * 128 + ((uint32_t)(j ^ (row & 7)) << 4);
            };
            uint32_t ahf[2][4], alf[2][4];
#pragma unroll
            for (int mt = 0; mt < 2; mt++) {
                int r16 = wm * 32 + mt * 16;
                LDSM_X4(ahf[mt][0], ahf[mt][1], ahf[mt][2], ahf[mt][3],
                        addr16(sb, r16));
                LDSM_X4(alf[mt][0], alf[mt][1], alf[mt][2], alf[mt][3],
                        addr16(sb + 16384, r16));
            }
#pragma unroll
            for (int ntp = 0; ntp < 2; ntp++) {
                int n16 = wn * 32 + ntp * 16;
                uint32_t bh0, bh1, bh2, bh3, bl0, bl1, bl2, bl3;
                LDSM_X4(bh0, bh1, bh2, bh3, addr16(sb + 32768, n16));
                LDSM_X4(bl0, bl1, bl2, bl3, addr16(sb + 40960, n16));
#pragma unroll
                for (int mt = 0; mt < 2; mt++) {
                    mma_bf16(acc[mt][2 * ntp],     ahf[mt], bh0, bh2);
                    mma_bf16(acc[mt][2 * ntp],     ahf[mt], bl0, bl2);
                    mma_bf16(acc[mt][2 * ntp],     alf[mt], bh0, bh2);
                    mma_bf16(acc[mt][2 * ntp + 1], ahf[mt], bh1, bh3);
                    mma_bf16(acc[mt][2 * ntp + 1], ahf[mt], bl1, bl3);
                    mma_bf16(acc[mt][2 * ntp + 1], alf[mt], bh1, bh3);
                }
            }
        }
        __syncthreads();
        if (ck + 2 < NC) issue(ck + 2, ck & 1);
    }

    const int qrow = lane >> 2;
#pragma unroll
    for (int mt = 0; mt < 2; mt++) {
#pragma unroll
        for (int nt = 0; nt < 4; nt++) {
            int row = bm + wm * 32 + mt * 16 + qrow;
            int col = bn + wn * 32 + nt * 8 + 2 * (lane & 3);
            size_t o0 = (size_t)row * Nn + col;
            size_t o1 = o0 + 8 * (size_t)Nn;
            float2 v0 = make_float2(acc[mt][nt][0], acc[mt][nt][1]);
            float2 v1 = make_float2(acc[mt][nt][2], acc[mt][nt][3]);
            if (EPI) {
                float2 r0 = *(const float2*)(Res + o0);
                float2 r1 = *(const float2*)(Res + o1);
                v0.x += r0.x; v0.y += r0.y;
                v1.x += r1.x; v1.y += r1.y;
            }
            *(float2*)(Cout + o0) = v0;
            *(float2*)(Cout + o1) = v1;
        }
    }
}

struct G4 {
    const __nv_bfloat16 *ah[4], *al[4], *bh[4], *bl[4];
    float* out[4];
};

__global__ __launch_bounds__(256, 2)
void gemm_mma4(G4 g, int Nn, int K)
{
    extern __shared__ char smem[];
    const int z = blockIdx.z;
    gemm_core<false>(g.ah[z], g.al[z], g.bh[z], g.bl[z], nullptr, g.out[z],
                     Nn, K, smem_u32(smem));
}

template<bool EPI>
__global__ __launch_bounds__(256, 2)
void gemm_mma(const __nv_bfloat16* __restrict__ Ah, const __nv_bfloat16* __restrict__ Al,
              const __nv_bfloat16* __restrict__ Bh, const __nv_bfloat16* __restrict__ Bl,
              const float* __restrict__ Res, float* __restrict__ Cout,
              int Nn, int K)
{
    extern __shared__ char smem[];
    gemm_core<EPI>(Ah, Al, Bh, Bl, Res, Cout, Nn, K, smem_u32(smem));
}

// ---------------- kernel 3: FUSED post ops + pair fusion → packed blocks ----
// One warp per (pair_row, head-pair): lanes 0-15 -> h=2hp, 16-31 -> 2hp+1.
// Each lane handles 4 channels of BOTH tokens of the pair. Does all per-channel
// post math (bf16 rounding points identical to reference), then the 2-token
// operator fusion, writing the packed scan block directly from registers.
__global__ void postpair_kernel(const float* __restrict__ w0,
                                const float* __restrict__ v0p,
                                const float* __restrict__ a0p)
{
    const int gw   = blockIdx.x * 8 + (threadIdx.x >> 5);   // prow*8 + hp
    const int lane = threadIdx.x & 31;
    const int prow = gw >> 3;
    const int hp   = gw & 7;
    const int h    = hp * 2 + (lane >> 4);
    const int li   = lane & 15;
    const int bb   = prow >> 10;
    const int p    = prow & (NP_ - 1);
    const size_t row1 = (size_t)bb * T_ + 2 * p;
    const int c0 = h * 64 + li * 4;

    const float4 w0v = *(const float4*)(w0  + c0);
    const float4 v0v = *(const float4*)(v0p + c0);
    const float4 a0v = *(const float4*)(a0p + c0);
    const float* w0a = &w0v.x; const float* v0a = &v0v.x; const float* a0a = &a0v.x;

    // k norms for both rows
    float4 kraw[2];
    kraw[0] = *(const float4*)(g_k + row1 * C_ + c0);
    kraw[1] = *(const float4*)(g_k + (row1 + 1) * C_ + c0);
    float np0 = fmaf(kraw[0].x, kraw[0].x, kraw[0].y * kraw[0].y)
              + fmaf(kraw[0].z, kraw[0].z, kraw[0].w * kraw[0].w);
    float np1 = fmaf(kraw[1].x, kraw[1].x, kraw[1].y * kraw[1].y)
              + fmaf(kraw[1].z, kraw[1].z, kraw[1].w * kraw[1].w);
#pragma unroll
    for (int off = 8; off; off >>= 1) {
        np0 += __shfl_xor_sync(0xffffffffu, np0, off);
        np1 += __shfl_xor_sync(0xffffffffu, np1, off);
    }
    float inv[2];
    inv[0] = 1.f / fmaxf(sqrtf(np0), 1e-12f);
    inv[1] = 1.f / fmaxf(sqrtf(np1), 1e-12f);

    float ews[2][4], vns[2][4], qs[2][4], ks[2][4], as_[2][4], bs[2][4];

#pragma unroll
    for (int r = 0; r < 2; r++) {
        const size_t row   = row1 + r;
        const size_t base  = row * C_ + c0;
        const size_t dbase = row * (4 * C_) + c0;
        float4 wdel = *(const float4*)(g_deltas + dbase);
        float4 vdel = *(const float4*)(g_deltas + dbase + 1024);
        float4 adel = *(const float4*)(g_deltas + dbase + 2048);
        float4 gdel = *(const float4*)(g_deltas + dbase + 3072);
        float4 vraw = *(const float4*)(g_v  + base);
        float4 vfr  = *(const float4*)(g_vf + base);
        float4 qraw = *(const float4*)(g_q  + base);
        const float* wd = &wdel.x; const float* vd = &vdel.x;
        const float* ad = &adel.x; const float* gd = &gdel.x;
        const float* kr = &kraw[r].x; const float* vr = &vraw.x;
        const float* vf = &vfr.x;  const float* qr = &qraw.x;

        float gs[4];
#pragma unroll
        for (int u = 0; u < 4; u++) {
            float xx = -(w0a[u] + wd[u]);
            float sp = (xx > 20.f) ? xx : log1pf(expf(xx));
            float logw = -expf(-sp - 0.5f);
            ews[r][u] = expf(__bfloat162float(__float2bfloat16(logw)));

            float sv = 1.f / (1.f + expf(-(v0a[u] + vd[u])));
            float vnew = vr[u] + (vf[u] - vr[u]) * sv;
            vns[r][u] = __bfloat162float(__float2bfloat16(vnew));

            float a = 1.f / (1.f + expf(-(a0a[u] + ad[u])));
            gs[u] = 1.f + gd[u];

            float kk = kr[u] * inv[r];
            ks[r][u]  = __bfloat162float(__float2bfloat16(kr[u] * a));
            as_[r][u] = __bfloat162float(__float2bfloat16(-kk));
            bs[r][u]  = __bfloat162float(__float2bfloat16(kk * a));
            qs[r][u]  = __bfloat162float(__float2bfloat16(qr[u]));
        }
        *(float4*)(g_gate + base) = make_float4(gs[0], gs[1], gs[2], gs[3]);
        __nv_bfloat162 v01 = __floats2bfloat162_rn(vns[r][0], vns[r][1]);
        __nv_bfloat162 v23 = __floats2bfloat162_rn(vns[r][2], vns[r][3]);
        uint2 vp;
        vp.x = *(const unsigned int*)&v01;
        vp.y = *(const unsigned int*)&v23;
        *(uint2*)(g_sv + base) = vp;
    }

    // rbq/rkq for both rows
    float rbq1 = 0.f, rkq1 = 0.f, rbq2 = 0.f, rkq2 = 0.f;
#pragma unroll
    for (int u = 0; u < 4; u++) {
        rbq1 = fmaf(qs[0][u], bs[0][u], rbq1);
        rkq1 = fmaf(qs[0][u], ks[0][u], rkq1);
        rbq2 = fmaf(qs[1][u], bs[1][u], rbq2);
        rkq2 = fmaf(qs[1][u], ks[1][u], rkq2);
    }
#pragma unroll
    for (int off = 8; off; off >>= 1) {
        rbq1 += __shfl_xor_sync(0xffffffffu, rbq1, off);
        rkq1 += __shfl_xor_sync(0xffffffffu, rkq1, off);
        rbq2 += __shfl_xor_sync(0xffffffffu, rbq2, off);
        rkq2 += __shfl_xor_sync(0xffffffffu, rkq2, off);
    }

    // qtilde = ew2*q2 + a2*rbq2
    float qt[4];
#pragma unroll
    for (int u = 0; u < 4; u++)
        qt[u] = fmaf(ews[1][u], qs[1][u], as_[1][u] * rbq2);

    float c1 = 0.f, c2 = 0.f, sc1 = 0.f, sc2 = 0.f;
#pragma unroll
    for (int u = 0; u < 4; u++) {
        c1  = fmaf(bs[0][u], as_[1][u], c1);
        c2  = fmaf(ks[0][u], as_[1][u], c2);
        sc1 = fmaf(bs[0][u], qt[u],  sc1);
        sc2 = fmaf(ks[0][u], qt[u],  sc2);
    }
#pragma unroll
    for (int off = 8; off; off >>= 1) {
        c1  += __shfl_xor_sync(0xffffffffu, c1,  off);
        c2  += __shfl_xor_sync(0xffffffffu, c2,  off);
        sc1 += __shfl_xor_sync(0xffffffffu, sc1, off);
        sc2 += __shfl_xor_sync(0xffffffffu, sc2, off);
    }

    float4 dd, aa, qw, qtv, v1, v3;
    float* ddp = &dd.x; float* aap = &aa.x; float* qwp = &qw.x;
    float* qtp = &qtv.x; float* v1p = &v1.x; float* v3p = &v3.x;
#pragma unroll
    for (int u = 0; u < 4; u++) {
        ddp[u] = ews[0][u] * ews[1][u];
        aap[u] = ews[0][u] * as_[1][u];
        qwp[u] = ews[0][u] * qs[0][u];
        qtp[u] = ews[0][u] * qt[u];
        v1p[u] = fmaf(bs[0][u], ews[1][u], c1 * bs[1][u]);
        v3p[u] = fmaf(ks[0][u], ews[1][u], c2 * bs[1][u]);
    }

    // packed bf16 operands: a1 (row1 -kk), b2, k2 (row2)
    __nv_bfloat162 a01 = __floats2bfloat162_rn(as_[0][0], as_[0][1]);
    __nv_bfloat162 a23 = __floats2bfloat162_rn(as_[0][2], as_[0][3]);
    __nv_bfloat162 b01 = __floats2bfloat162_rn(bs[1][0], bs[1][1]);
    __nv_bfloat162 b23 = __floats2bfloat162_rn(bs[1][2], bs[1][3]);
    __nv_bfloat162 k01 = __floats2bfloat162_rn(ks[1][0], ks[1][1]);
    __nv_bfloat162 k23 = __floats2bfloat162_rn(ks[1][2], ks[1][3]);
    __nv_bfloat162 s101 = __floats2bfloat162_rn(vns[0][0], vns[0][1]);
    __nv_bfloat162 s123 = __floats2bfloat162_rn(vns[0][2], vns[0][3]);
    __nv_bfloat162 s201 = __floats2bfloat162_rn(vns[1][0], vns[1][1]);
    __nv_bfloat162 s223 = __floats2bfloat162_rn(vns[1][2], vns[1][3]);

    char* gp = g_pack + ((size_t)prow * H_ + h) * PACKB_;
    *(float4*)(gp + 0    + 16 * li) = dd;
    *(float4*)(gp + 256  + 16 * li) = aa;
    *(float4*)(gp + 512  + 16 * li) = qw;
    *(float4*)(gp + 768  + 16 * li) = qtv;
    *(float4*)(gp + 1024 + 16 * li) = v1;
    *(float4*)(gp + 1280 + 16 * li) = v3;
    *(uint2*)(gp + 1536 + 8 * li) = make_uint2(*(const unsigned int*)&a01,
                                               *(const unsigned int*)&a23);
    *(uint2*)(gp + 1664 + 8 * li) = make_uint2(*(const unsigned int*)&b01,
                                               *(const unsigned int*)&b23);
    *(uint2*)(gp + 1792 + 8 * li) = make_uint2(*(const unsigned int*)&k01,
                                               *(const unsigned int*)&k23);
    *(uint2*)(gp + 1952 + 8 * li) = make_uint2(*(const unsigned int*)&s101,
                                               *(const unsigned int*)&s123);
    *(uint2*)(gp + 2080 + 8 * li) = make_uint2(*(const unsigned int*)&s201,
                                               *(const unsigned int*)&s223);
    if (li == 0) {
        *(float4*)(gp + 1920) = make_float4(rbq1, rkq1, sc1, sc2);
        *(float*)(gp + 1936)  = rkq2;
    }
}

// ---------------- kernel 4: pair-fused scan, dual-chain per warp -------------
// grid (32, 4); blockDim 64 (2 warps, 128 blocks, 256 warps). Each warp holds
// EIGHT value rows as two independent 4-row chains (A: rbase+quarter,
// B: rbase+4+quarter) over the SAME operand stream: one smem ring serves both,
// halving pack traffic, and the two dependency chains interleave in the
// instruction stream so chain B's FMAs issue under chain A's shfl latency.
#define SRING_ 8
#define SCAN_SMEM (2 * SRING_ * PACKB_)   // 40960 B

__global__ __launch_bounds__(64)
void scan_kernel()
{
    extern __shared__ char ssm[];
    const int bh = blockIdx.x;
    const int b = bh >> 4, h = bh & 15;
    const int wid  = threadIdx.x >> 5;
    const int lane = threadIdx.x & 31;
    const int quarter = lane >> 3;
    const int li2  = lane & 7;
    const int rbase = blockIdx.y * 16 + wid * 8;
    const int vrowA = rbase + quarter;
    const int vrowB = rbase + 4 + quarter;

    const size_t packbh = ((size_t)(b * NP_) * H_ + h) * PACKB_;
    const size_t ybA = (size_t)b * T_ * C_ + h * 64 + vrowA;
    const size_t ybB = (size_t)b * T_ * C_ + h * 64 + vrowB;
    const uint32_t ring = smem_u32(ssm) + (uint32_t)wid * (SRING_ * PACKB_);

    auto issue_pair = [&](int p) {
        const char* src = g_pack + packbh + (size_t)p * PSTR_ + lane * 16;
        const uint32_t dst = ring + (uint32_t)(p & (SRING_ - 1)) * PACKB_ + lane * 16;
#pragma unroll
        for (int c = 0; c < 5; c++)
            CPA16(dst + c * 512, src + c * 512);
    };

#pragma unroll
    for (int p = 0; p < 7; p++) { issue_pair(p); CPA_COMMIT(); }

    float sA[8], sB[8];
#pragma unroll
    for (int i = 0; i < 8; i++) { sA[i] = 0.f; sB[i] = 0.f; }

    const uint32_t oA  = li2 * 32;
    const uint32_t oU  = li2 * 16;

    CPA_WAIT(6);
    __syncwarp();
    uint4  Ppa;
    float4 Paa0, Paa1, Pqw0, Pqw1, Pqt0, Pqt1;
    {
        const uint32_t st0 = ring;
        Ppa  = lds128u(st0 + 1536 + oU);
        Paa0 = lds128f(st0 + 256 + oA); Paa1 = lds128f(st0 + 256 + oA + 16);
        Pqw0 = lds128f(st0 + 512 + oA); Pqw1 = lds128f(st0 + 512 + oA + 16);
        Pqt0 = lds128f(st0 + 768 + oA); Pqt1 = lds128f(st0 + 768 + oA + 16);
    }

    for (int p = 0; p < NP_; p++) {
        const uint32_t st = ring + (uint32_t)(p & (SRING_ - 1)) * PACKB_;

        const uint4  paU = Ppa;
        const float4 aa0 = Paa0, aa1 = Paa1;
        const float4 qw0 = Pqw0, qw1 = Pqw1;
        const float4 qt0 = Pqt0, qt1 = Pqt1;

        CPA_WAIT(5);
        __syncwarp();
        {
            int pf = p + 1; if (pf > NP_ - 1) pf = NP_ - 1;
            const uint32_t stn = ring + (uint32_t)(pf & (SRING_ - 1)) * PACKB_;
            Ppa  = lds128u(stn + 1536 + oU);
            Paa0 = lds128f(stn + 256 + oA); Paa1 = lds128f(stn + 256 + oA + 16);
            Pqw0 = lds128f(stn + 512 + oA); Pqw1 = lds128f(stn + 512 + oA + 16);
            Pqt0 = lds128f(stn + 768 + oA); Pqt1 = lds128f(stn + 768 + oA + 16);
        }

        {
            int pn = p + 7;
            if (pn < NP_) issue_pair(pn);
            CPA_COMMIT();
        }

        // update-phase LDS (shared by both chains; vv per-row)
        const float vvA1 = ldsbf16(st + 1952 + vrowA * 2);
        const float vvA2 = ldsbf16(st + 2080 + vrowA * 2);
        const float vvB1 = ldsbf16(st + 1952 + vrowB * 2);
        const float vvB2 = ldsbf16(st + 2080 + vrowB * 2);
        const uint4 pbU = lds128u(st + 1664 + oU);
        const uint4 pkU = lds128u(st + 1792 + oU);
        const float4 dd0 = lds128f(st + 0 + oA),    dd1 = lds128f(st + 0 + oA + 16);
        const float4 v10 = lds128f(st + 1024 + oA), v11 = lds128f(st + 1024 + oA + 16);
        const float4 v30 = lds128f(st + 1280 + oA), v31 = lds128f(st + 1280 + oA + 16);
        const float4 sc4 = lds128f(st + 1920);
        const float rkq2 = ldsf32(st + 1936);

        float2 a01 = bf2(paU.x), a23 = bf2(paU.y), a45 = bf2(paU.z), a67 = bf2(paU.w);

        float r1A = ((sA[0]*a01.x + sA[1]*a01.y) + (sA[2]*a23.x + sA[3]*a23.y))
                  + ((sA[4]*a45.x + sA[5]*a45.y) + (sA[6]*a67.x + sA[7]*a67.y));
        float r1B = ((sB[0]*a01.x + sB[1]*a01.y) + (sB[2]*a23.x + sB[3]*a23.y))
                  + ((sB[4]*a45.x + sB[5]*a45.y) + (sB[6]*a67.x + sB[7]*a67.y));
        float r2A = ((sA[0]*aa0.x + sA[1]*aa0.y) + (sA[2]*aa0.z + sA[3]*aa0.w))
                  + ((sA[4]*aa1.x + sA[5]*aa1.y) + (sA[6]*aa1.z + sA[7]*aa1.w));
        float r2B = ((sB[0]*aa0.x + sB[1]*aa0.y) + (sB[2]*aa0.z + sB[3]*aa0.w))
                  + ((sB[4]*aa1.x + sB[5]*aa1.y) + (sB[6]*aa1.z + sB[7]*aa1.w));
        float r3A = ((sA[0]*qw0.x + sA[1]*qw0.y) + (sA[2]*qw0.z + sA[3]*qw0.w))
                  + ((sA[4]*qw1.x + sA[5]*qw1.y) + (sA[6]*qw1.z + sA[7]*qw1.w));
        float r3B = ((sB[0]*qw0.x + sB[1]*qw0.y) + (sB[2]*qw0.z + sB[3]*qw0.w))
                  + ((sB[4]*qw1.x + sB[5]*qw1.y) + (sB[6]*qw1.z + sB[7]*qw1.w));
        float r4A = ((sA[0]*qt0.x + sA[1]*qt0.y) + (sA[2]*qt0.z + sA[3]*qt0.w))
                  + ((sA[4]*qt1.x + sA[5]*qt1.y) + (sA[6]*qt1.z + sA[7]*qt1.w));
        float r4B = ((sB[0]*qt0.x + sB[1]*qt0.y) + (sB[2]*qt0.z + sB[3]*qt0.w))
                  + ((sB[4]*qt1.x + sB[5]*qt1.y) + (sB[6]*qt1.z + sB[7]*qt1.w));

#pragma unroll
        for (int off = 4; off; off >>= 1) {
            r1A += __shfl_xor_sync(0xffffffffu, r1A, off);
            r1B += __shfl_xor_sync(0xffffffffu, r1B, off);
            r2A += __shfl_xor_sync(0xffffffffu, r2A, off);
            r2B += __shfl_xor_sync(0xffffffffu, r2B, off);
            r3A += __shfl_xor_sync(0xffffffffu, r3A, off);
            r3B += __shfl_xor_sync(0xffffffffu, r3B, off);
            r4A += __shfl_xor_sync(0xffffffffu, r4A, off);
            r4B += __shfl_xor_sync(0xffffffffu, r4B, off);
        }

        float2 b01 = bf2(pbU.x), b23 = bf2(pbU.y), b45 = bf2(pbU.z), b67 = bf2(pbU.w);
        float2 k01 = bf2(pkU.x), k23 = bf2(pkU.y), k45 = bf2(pkU.z), k67 = bf2(pkU.w);

        sA[0] = sA[0]*dd0.x + r1A*v10.x + r2A*b01.x + vvA1*v30.x + vvA2*k01.x;
        sB[0] = sB[0]*dd0.x + r1B*v10.x + r2B*b01.x + vvB1*v30.x + vvB2*k01.x;
        sA[1] = sA[1]*dd0.y + r1A*v10.y + r2A*b01.y + vvA1*v30.y + vvA2*k01.y;
        sB[1] = sB[1]*dd0.y + r1B*v10.y + r2B*b01.y + vvB1*v30.y + vvB2*k01.y;
        sA[2] = sA[2]*dd0.z + r1A*v10.z + r2A*b23.x + vvA1*v30.z + vvA2*k23.x;
        sB[2] = sB[2]*dd0.z + r1B*v10.z + r2B*b23.x + vvB1*v30.z + vvB2*k23.x;
        sA[3] = sA[3]*dd0.w + r1A*v10.w + r2A*b23.y + vvA1*v30.w + vvA2*k23.y;
        sB[3] = sB[3]*dd0.w + r1B*v10.w + r2B*b23.y + vvB1*v30.w + vvB2*k23.y;
        sA[4] = sA[4]*dd1.x + r1A*v11.x + r2A*b45.x + vvA1*v31.x + vvA2*k45.x;
        sB[4] = sB[4]*dd1.x + r1B*v11.x + r2B*b45.x + vvB1*v31.x + vvB2*k45.x;
        sA[5] = sA[5]*dd1.y + r1A*v11.y + r2A*b45.y + vvA1*v31.y + vvA2*k45.y;
        sB[5] = sB[5]*dd1.y + r1B*v11.y + r2B*b45.y + vvB1*v31.y + vvB2*k45.y;
        sA[6] = sA[6]*dd1.z + r1A*v11.z + r2A*b67.x + vvA1*v31.z + vvA2*k67.x;
        sB[6] = sB[6]*dd1.z + r1B*v11.z + r2B*b67.x + vvB1*v31.z + vvB2*k67.x;
        sA[7] = sA[7]*dd1.w + r1A*v11.w + r2A*b67.y + vvA1*v31.w + vvA2*k67.y;
        sB[7] = sB[7]*dd1.w + r1B*v11.w + r2B*b67.y + vvB1*v31.w + vvB2*k67.y;

        if (li2 == 0) {
            g_yscan[ybA + (size_t)(2 * p)     * C_] =
                fmaf(r1A, sc4.x, fmaf(vvA1, sc4.y, r3A));
            g_yscan[ybA + (size_t)(2 * p + 1) * C_] =
                fmaf(r1A, sc4.z, fmaf(vvA1, sc4.w, fmaf(vvA2, rkq2, r4A)));
            g_yscan[ybB + (size_t)(2 * p)     * C_] =
                fmaf(r1B, sc4.x, fmaf(vvB1, sc4.y, r3B));
            g_yscan[ybB + (size_t)(2 * p + 1) * C_] =
                fmaf(r1B, sc4.z, fmaf(vvB1, sc4.w, fmaf(vvB2, rkq2, r4B)));
        }
    }
}

// ---------------- kernel 5: y corrections (emit bf16 hi/lo) ----------------
__global__ void ycorr_kernel(const float* __restrict__ x,
                             const float* __restrict__ r_k)
{
    const int gh   = blockIdx.x * 8 + (threadIdx.x >> 5);
    const int lane = threadIdx.x & 31;
    const int i = gh >> 4, h = gh & 15;
    const size_t base = (size_t)i * C_ + h * 64 + lane * 2;

    float x0v = x[base], x1v = x[base + 1];
    float v0v = __bfloat162float(g_sv[base]);
    float v1v = __bfloat162float(g_sv[base + 1]);

    float xs = x0v * x0v + x1v * x1v;
    float vs = v0v * v0v + v1v * v1v;
#pragma unroll
    for (int off = 16; off; off >>= 1) {
        xs += __shfl_xor_sync(0xffffffffu, xs, off);
        vs += __shfl_xor_sync(0xffffffffu, vs, off);
    }
    float xnorm = sqrtf(xs);
    float vnorm = sqrtf(vs);
    float un = 1.f - xnorm / (vnorm + 1e-12f);

    float rk0 = r_k[h * 64 + lane * 2];
    float rk1 = r_k[h * 64 + lane * 2 + 1];
    float u0 = un / (1.f + expf(-rk0));
    float u1 = un / (1.f + expf(-rk1));

    const float scale = 0.125f;
    float y0 = (g_yscan[base]     * scale + v0v * u0) * g_gate[base];
    float y1 = (g_yscan[base + 1] * scale + v1v * u1) * g_gate[base + 1];
    f2hl(y0, g_yfh[base],     g_yfl[base]);
    f2hl(y1, g_yfh[base + 1], g_yfl[base + 1]);
}

// ---------------- launch ----------------------------------------------------
extern "C" void kernel_launch(void* const* d_in, const int* in_sizes, int n_in,
                              void* d_out, int out_size)
{
    const float* residual = (const float*)d_in[0];
    const float* x        = (const float*)d_in[1];
    const float* x0       = (const float*)d_in[2];
    const float* dx0      = (const float*)d_in[3];
    const float* Wq       = (const float*)d_in[4];
    const float* Wk       = (const float*)d_in[5];
    const float* Wv       = (const float*)d_in[6];
    const float* Wproj    = (const float*)d_in[7];
    const float* x_q      = (const float*)d_in[8];
    const float* x_k      = (const float*)d_in[9];
    const float* x_v      = (const float*)d_in[10];
    const float* v0       = (const float*)d_in[11];
    const float* w0       = (const float*)d_in[12];
    const float* a0       = (const float*)d_in[13];
    const float* miss     = (const float*)d_in[14];
    const float* r_k      = (const float*)d_in[15];
    float* out = (float*)d_out;

    __nv_bfloat16 *xqh, *xql, *xkh, *xkl, *xvh, *xvl, *x0h, *x0l;
    __nv_bfloat16 *wqh, *wql, *wkh, *wkl, *wvh, *wvl, *wph, *wpl;
    __nv_bfloat16 *xh, *xl, *mth, *mtl, *yfh, *yfl;
    float *pq, *pk, *pv, *pvf, *pdel;
    cudaGetSymbolAddress((void**)&xqh, g_xqh); cudaGetSymbolAddress((void**)&xql, g_xql);
    cudaGetSymbolAddress((void**)&xkh, g_xkh); cudaGetSymbolAddress((void**)&xkl, g_xkl);
    cudaGetSymbolAddress((void**)&xvh, g_xvh); cudaGetSymbolAddress((void**)&xvl, g_xvl);
    cudaGetSymbolAddress((void**)&x0h, g_x0h); cudaGetSymbolAddress((void**)&x0l, g_x0l);
    cudaGetSymbolAddress((void**)&wqh, g_wqh); cudaGetSymbolAddress((void**)&wql, g_wql);
    cudaGetSymbolAddress((void**)&wkh, g_wkh); cudaGetSymbolAddress((void**)&wkl, g_wkl);
    cudaGetSymbolAddress((void**)&wvh, g_wvh); cudaGetSymbolAddress((void**)&wvl, g_wvl);
    cudaGetSymbolAddress((void**)&wph, g_wph); cudaGetSymbolAddress((void**)&wpl, g_wpl);
    cudaGetSymbolAddress((void**)&xh,  g_xh);  cudaGetSymbolAddress((void**)&xl,  g_xl);
    cudaGetSymbolAddress((void**)&mth, g_mth); cudaGetSymbolAddress((void**)&mtl, g_mtl);
    cudaGetSymbolAddress((void**)&yfh, g_yfh); cudaGetSymbolAddress((void**)&yfl, g_yfl);
    cudaGetSymbolAddress((void**)&pq,  g_q);   cudaGetSymbolAddress((void**)&pk,  g_k);
    cudaGetSymbolAddress((void**)&pv,  g_v);   cudaGetSymbolAddress((void**)&pvf, g_vf);
    cudaGetSymbolAddress((void**)&pdel, g_deltas);

    cudaFuncSetAttribute(gemm_mma4, cudaFuncAttributeMaxDynamicSharedMemorySize, GSMEM_BYTES);
    cudaFuncSetAttribute(gemm_mma<false>, cudaFuncAttributeMaxDynamicSharedMemorySize, GSMEM_BYTES);
    cudaFuncSetAttribute(gemm_mma<true>,  cudaFuncAttributeMaxDynamicSharedMemorySize, GSMEM_BYTES);
    cudaFuncSetAttribute(scan_kernel, cudaFuncAttributeMaxDynamicSharedMemorySize, SCAN_SMEM);

    // conversions (independent)
    conv_w4<<<4 * C_ * C_ / 256, 256>>>(Wq, Wk, Wv, Wproj);
    conv_xmt<<<2 * ROWS_ * 128 / 256, 256>>>(x, miss);
    prep_kernel<<<ELEMS_ / 256, 256>>>(x, x0, dx0, x_q, x_k, x_v);

    // fused projections: [4096,1024] = A @ W^T, K=1024, 4 operand sets
    G4 g4;
    g4.ah[0] = xqh; g4.al[0] = xql; g4.bh[0] = wqh; g4.bl[0] = wql; g4.out[0] = pq;
    g4.ah[1] = xkh; g4.al[1] = xkl; g4.bh[1] = wkh; g4.bl[1] = wkl; g4.out[1] = pk;
    g4.ah[2] = xvh; g4.al[2] = xvl; g4.bh[2] = wvh; g4.bl[2] = wvl; g4.out[2] = pv;
    g4.ah[3] = x0h; g4.al[3] = x0l; g4.bh[3] = wvh; g4.bl[3] = wvl; g4.out[3] = pvf;
    gemm_mma4<<<dim3(C_ / 64, ROWS_ / 128, 4), 256, GSMEM_BYTES>>>(g4, C_, C_);

    // deltas: [4096,4096] = x[:, :128] @ missT^T, K=128
    dim3 gD(4 * C_ / 64, ROWS_ / 128);
    gemm_mma<false><<<gD, 256, GSMEM_BYTES>>>(xh, xl, mth, mtl, nullptr, pdel, 4 * C_, 128);

    // fused post ops + pair fusion → packed operand blocks
    postpair_kernel<<<NPROW_ * 8 / 8, 256>>>(w0, v0, a0);

    // dual-chain pair-fused scan
    scan_kernel<<<dim3(B_ * H_, 4), 64, SCAN_SMEM>>>();

    // corrections + gate (emits yfin hi/lo)
    ycorr_kernel<<<ROWS_ * H_ / 8, 256>>>(x, r_k);

    // out = residual + yfin @ Wproj^T
    gemm_mma<true><<<dim3(C_ / 64, ROWS_ / 128), 256, GSMEM_BYTES>>>(
        yfh, yfl, wph, wpl, residual, out, C_, C_);
}

// round 15
// speedup vs baseline: 1.0941x; 1.0941x over previous
#include <cuda_runtime.h>
#include <cuda_bf16.h>
#include <math.h>
#include <stdint.h>

// Problem constants
#define B_ 2
#define T_ 2048
#define C_ 1024
#define H_ 16
#define ROWS_ (B_*T_)            // 4096
#define ELEMS_ (ROWS_*C_)        // 4194304
#define NPROW_ (ROWS_/2)         // 2048 pair-rows
#define NP_ (T_/2)               // 1024 pairs per batch

// packed per-(pair,head) scan operand block
#define PACKB_ 2560
#define PSTR_  ((size_t)H_ * PACKB_)   // stride between consecutive pairs

// ---------------- scratch (device globals; no cudaMalloc allowed) ----------
__device__ float g_q  [ELEMS_];
__device__ float g_k  [ELEMS_];
__device__ float g_v  [ELEMS_];
__device__ float g_vf [ELEMS_];
__device__ float g_deltas[(size_t)ROWS_*4*C_];   // [4096, 4096]
__device__ float g_gate[ELEMS_];
__device__ float g_yscan[ELEMS_];
__device__ __nv_bfloat16 g_sv[ELEMS_];
__device__ char  g_pack[(size_t)NPROW_*H_*PACKB_];   // ~84 MB

// bf16 hi/lo operand buffers for bf16x3 GEMMs
__device__ __nv_bfloat16 g_xqh[ELEMS_], g_xql[ELEMS_];
__device__ __nv_bfloat16 g_xkh[ELEMS_], g_xkl[ELEMS_];
__device__ __nv_bfloat16 g_xvh[ELEMS_], g_xvl[ELEMS_];
__device__ __nv_bfloat16 g_x0h[ELEMS_], g_x0l[ELEMS_];
__device__ __nv_bfloat16 g_wqh[C_*C_],  g_wql[C_*C_];
__device__ __nv_bfloat16 g_wkh[C_*C_],  g_wkl[C_*C_];
__device__ __nv_bfloat16 g_wvh[C_*C_],  g_wvl[C_*C_];
__device__ __nv_bfloat16 g_wph[C_*C_],  g_wpl[C_*C_];
__device__ __nv_bfloat16 g_xh [ROWS_*128], g_xl [ROWS_*128];
__device__ __nv_bfloat16 g_mth[4*C_*128],  g_mtl[4*C_*128];
__device__ __nv_bfloat16 g_yfh[ELEMS_], g_yfl[ELEMS_];

// ---------------- helpers ----------------------------------------------------
__device__ __forceinline__ uint32_t smem_u32(const void* p) {
    uint32_t a;
    asm("{ .reg .u64 t; cvta.to.shared.u64 t, %1; cvt.u32.u64 %0, t; }"
        : "=r"(a) : "l"(p));
    return a;
}
#define CPA16(dst32, src) \
    asm volatile("cp.async.cg.shared.global [%0], [%1], 16;" \
                 :: "r"(dst32), "l"(src))
#define CPA_COMMIT() asm volatile("cp.async.commit_group;" ::: "memory")
#define CPA_WAIT(n)  asm volatile("cp.async.wait_group %0;" :: "n"(n) : "memory")

#define LDSM_X4(r0, r1, r2, r3, addr) \
    asm volatile("ldmatrix.sync.aligned.m8n8.x4.shared.b16 {%0,%1,%2,%3}, [%4];" \
                 : "=r"(r0), "=r"(r1), "=r"(r2), "=r"(r3) : "r"(addr))

__device__ __forceinline__ float4 lds128f(uint32_t a) {
    float4 v;
    asm volatile("ld.shared.v4.f32 {%0,%1,%2,%3}, [%4];"
                 : "=f"(v.x), "=f"(v.y), "=f"(v.z), "=f"(v.w) : "r"(a));
    return v;
}
__device__ __forceinline__ uint4 lds128u(uint32_t a) {
    uint4 v;
    asm volatile("ld.shared.v4.u32 {%0,%1,%2,%3}, [%4];"
                 : "=r"(v.x), "=r"(v.y), "=r"(v.z), "=r"(v.w) : "r"(a));
    return v;
}
__device__ __forceinline__ float ldsf32(uint32_t a) {
    float v;
    asm volatile("ld.shared.f32 %0, [%1];" : "=f"(v) : "r"(a));
    return v;
}
__device__ __forceinline__ float ldsbf16(uint32_t a) {
    unsigned short v;
    asm volatile("ld.shared.u16 %0, [%1];" : "=h"(v) : "r"(a));
    __nv_bfloat16 b = *reinterpret_cast<__nv_bfloat16*>(&v);
    return __bfloat162float(b);
}

__device__ __forceinline__ void mma_bf16(float* c, const uint32_t* a,
                                         uint32_t b0, uint32_t b1) {
    asm volatile(
        "mma.sync.aligned.m16n8k16.row.col.f32.bf16.bf16.f32 "
        "{%0,%1,%2,%3}, {%4,%5,%6,%7}, {%8,%9}, {%0,%1,%2,%3};"
        : "+f"(c[0]), "+f"(c[1]), "+f"(c[2]), "+f"(c[3])
        : "r"(a[0]), "r"(a[1]), "r"(a[2]), "r"(a[3]), "r"(b0), "r"(b1));
}

__device__ __forceinline__ void f2hl(float v, __nv_bfloat16& h, __nv_bfloat16& l) {
    h = __float2bfloat16(v);
    l = __float2bfloat16(v - __bfloat162float(h));
}
__device__ __forceinline__ float2 bf2(uint32_t u) {
    return __bfloat1622float2(*(const __nv_bfloat162*)&u);
}

// ---------------- conversion kernels ----------------------------------------
__global__ void conv_w4(const float* __restrict__ Wq, const float* __restrict__ Wk,
                        const float* __restrict__ Wv, const float* __restrict__ Wp)
{
    int i = blockIdx.x * blockDim.x + threadIdx.x;
    int sel = i >> 20;
    int j = i & (C_ * C_ - 1);
    switch (sel) {
        case 0: f2hl(Wq[j], g_wqh[j], g_wql[j]); break;
        case 1: f2hl(Wk[j], g_wkh[j], g_wkl[j]); break;
        case 2: f2hl(Wv[j], g_wvh[j], g_wvl[j]); break;
        default: f2hl(Wp[j], g_wph[j], g_wpl[j]); break;
    }
}

__global__ void conv_xmt(const float* __restrict__ x, const float* __restrict__ miss)
{
    int i = blockIdx.x * blockDim.x + threadIdx.x;
    if (i < ROWS_ * 128) {
        int row = i >> 7, c = i & 127;
        f2hl(x[(size_t)row * C_ + c], g_xh[i], g_xl[i]);
    } else {
        int j = i - ROWS_ * 128;
        int nrow = j >> 7, k = j & 127;
        f2hl(miss[(size_t)k * (4 * C_) + nrow], g_mth[j], g_mtl[j]);
    }
}

// ---------------- kernel 1: token shift + mixes (emit bf16 hi/lo) ----------
__global__ void prep_kernel(const float* __restrict__ x,
                            const float* __restrict__ x0,
                            const float* __restrict__ dx0,
                            const float* __restrict__ mq,
                            const float* __restrict__ mk,
                            const float* __restrict__ mv)
{
    int idx = blockIdx.x * blockDim.x + threadIdx.x;
    if (idx >= ELEMS_) return;
    int c   = idx & (C_ - 1);
    int row = idx >> 10;
    int t   = row & (T_ - 1);
    float xc = x[idx];
    float xp = (t == 0) ? 0.f : x[idx - C_];
    float dx = xp - xc;
    f2hl(xc + dx * mq[c],            g_xqh[idx], g_xql[idx]);
    f2hl(xc + dx * mk[c],            g_xkh[idx], g_xkl[idx]);
    f2hl(xc + dx * mv[c],            g_xvh[idx], g_xvl[idx]);
    f2hl(x0[idx] + dx0[idx] * mv[c], g_x0h[idx], g_x0l[idx]);
}

// ---------------- GEMM core: mma.sync bf16x3, 128x64 tile, 2 CTAs/SM --------
#define GSTAGE_ (49152)
#define GSMEM_BYTES (2 * GSTAGE_)

template<bool EPI>
__device__ __forceinline__
void gemm_core(const __nv_bfloat16* __restrict__ Ah, const __nv_bfloat16* __restrict__ Al,
               const __nv_bfloat16* __restrict__ Bh, const __nv_bfloat16* __restrict__ Bl,
               const float* __restrict__ Res, float* __restrict__ Cout,
               int Nn, int K, uint32_t smem32)
{
    const int tid  = threadIdx.x;
    const int wid  = tid >> 5;
    const int lane = tid & 31;
    const int wm   = wid >> 1;
    const int wn   = wid & 1;
    const int bm   = blockIdx.y * 128;
    const int bn   = blockIdx.x * 64;
    const int NC   = K >> 6;

    const int lrow = ((lane >> 3) & 1) * 8 + (lane & 7);
    const int lkof = (lane >> 4);

    auto issue = [&](int ck, int s) {
        const int kcol = ck * 64;
        const uint32_t sb = smem32 + (uint32_t)s * GSTAGE_;
#pragma unroll
        for (int t = 0; t < 2; t++) {
            const __nv_bfloat16* gp = t ? Al : Ah;
#pragma unroll
            for (int i = 0; i < 4; i++) {
                int id  = tid + i * 256;
                int row = id >> 3;
                int j   = id & 7;
                uint32_t dst = sb + (uint32_t)t * 16384 + row * 128
                             + ((uint32_t)(j ^ (row & 7)) << 4);
                const void* src = gp + (size_t)(bm + row) * K + kcol + j * 8;
                CPA16(dst, src);
            }
        }
#pragma unroll
        for (int t = 0; t < 2; t++) {
            const __nv_bfloat16* gp = t ? Bl : Bh;
#pragma unroll
            for (int i = 0; i < 2; i++) {
                int id  = tid + i * 256;
                int row = id >> 3;
                int j   = id & 7;
                uint32_t dst = sb + 32768u + (uint32_t)t * 8192 + row * 128
                             + ((uint32_t)(j ^ (row & 7)) << 4);
                const void* src = gp + (size_t)(bn + row) * K + kcol + j * 8;
                CPA16(dst, src);
            }
        }
        CPA_COMMIT();
    };

    float acc[2][4][4];
#pragma unroll
    for (int mt = 0; mt < 2; mt++)
#pragma unroll
        for (int nt = 0; nt < 4; nt++)
#pragma unroll
            for (int r = 0; r < 4; r++) acc[mt][nt][r] = 0.f;

    issue(0, 0);
    if (NC > 1) issue(1, 1);

    for (int ck = 0; ck < NC; ck++) {
        if (ck + 1 < NC) { CPA_WAIT(1); } else { CPA_WAIT(0); }
        __syncthreads();

        const uint32_t sb = smem32 + (uint32_t)(ck & 1) * GSTAGE_;

#pragma unroll
        for (int ks = 0; ks < 4; ks++) {
            auto addr16 = [&](uint32_t tbase, int row16) -> uint32_t {
                int row = row16 + lrow;
                int j   = ks * 2 + lkof;
                return tbase + row * 128 + ((uint32_t)(j ^ (row & 7)) << 4);
            };
            uint32_t ahf[2][4], alf[2][4];
#pragma unroll
            for (int mt = 0; mt < 2; mt++) {
                int r16 = wm * 32 + mt * 16;
                LDSM_X4(ahf[mt][0], ahf[mt][1], ahf[mt][2], ahf[mt][3],
                        addr16(sb, r16));
                LDSM_X4(alf[mt][0], alf[mt][1], alf[mt][2], alf[mt][3],
                        addr16(sb + 16384, r16));
            }
#pragma unroll
            for (int ntp = 0; ntp < 2; ntp++) {
                int n16 = wn * 32 + ntp * 16;
                uint32_t bh0, bh1, bh2, bh3, bl0, bl1, bl2, bl3;
                LDSM_X4(bh0, bh1, bh2, bh3, addr16(sb + 32768, n16));
                LDSM_X4(bl0, bl1, bl2, bl3, addr16(sb + 40960, n16));
#pragma unroll
                for (int mt = 0; mt < 2; mt++) {
                    mma_bf16(acc[mt][2 * ntp],     ahf[mt], bh0, bh2);
                    mma_bf16(acc[mt][2 * ntp],     ahf[mt], bl0, bl2);
                    mma_bf16(acc[mt][2 * ntp],     alf[mt], bh0, bh2);
                    mma_bf16(acc[mt][2 * ntp + 1], ahf[mt], bh1, bh3);
                    mma_bf16(acc[mt][2 * ntp + 1], ahf[mt], bl1, bl3);
                    mma_bf16(acc[mt][2 * ntp + 1], alf[mt], bh1, bh3);
                }
            }
        }
        __syncthreads();
        if (ck + 2 < NC) issue(ck + 2, ck & 1);
    }

    const int qrow = lane >> 2;
#pragma unroll
    for (int mt = 0; mt < 2; mt++) {
#pragma unroll
        for (int nt = 0; nt < 4; nt++) {
            int row = bm + wm * 32 + mt * 16 + qrow;
            int col = bn + wn * 32 + nt * 8 + 2 * (lane & 3);
            size_t o0 = (size_t)row * Nn + col;
            size_t o1 = o0 + 8 * (size_t)Nn;
            float2 v0 = make_float2(acc[mt][nt][0], acc[mt][nt][1]);
            float2 v1 = make_float2(acc[mt][nt][2], acc[mt][nt][3]);
            if (EPI) {
                float2 r0 = *(const float2*)(Res + o0);
                float2 r1 = *(const float2*)(Res + o1);
                v0.x += r0.x; v0.y += r0.y;
                v1.x += r1.x; v1.y += r1.y;
            }
            *(float2*)(Cout + o0) = v0;
            *(float2*)(Cout + o1) = v1;
        }
    }
}

struct G4 {
    const __nv_bfloat16 *ah[4], *al[4], *bh[4], *bl[4];
    float* out[4];
};

__global__ __launch_bounds__(256, 2)
void gemm_mma4(G4 g, int Nn, int K)
{
    extern __shared__ char smem[];
    const int z = blockIdx.z;
    gemm_core<false>(g.ah[z], g.al[z], g.bh[z], g.bl[z], nullptr, g.out[z],
                     Nn, K, smem_u32(smem));
}

template<bool EPI>
__global__ __launch_bounds__(256, 2)
void gemm_mma(const __nv_bfloat16* __restrict__ Ah, const __nv_bfloat16* __restrict__ Al,
              const __nv_bfloat16* __restrict__ Bh, const __nv_bfloat16* __restrict__ Bl,
              const float* __restrict__ Res, float* __restrict__ Cout,
              int Nn, int K)
{
    extern __shared__ char smem[];
    gemm_core<EPI>(Ah, Al, Bh, Bl, Res, Cout, Nn, K, smem_u32(smem));
}

// ---------------- kernel 3: FUSED post ops + pair fusion → packed blocks ----
__global__ void postpair_kernel(const float* __restrict__ w0,
                                const float* __restrict__ v0p,
                                const float* __restrict__ a0p)
{
    const int gw   = blockIdx.x * 8 + (threadIdx.x >> 5);   // prow*8 + hp
    const int lane = threadIdx.x & 31;
    const int prow = gw >> 3;
    const int hp   = gw & 7;
    const int h    = hp * 2 + (lane >> 4);
    const int li   = lane & 15;
    const int bb   = prow >> 10;
    const int p    = prow & (NP_ - 1);
    const size_t row1 = (size_t)bb * T_ + 2 * p;
    const int c0 = h * 64 + li * 4;

    const float4 w0v = *(const float4*)(w0  + c0);
    const float4 v0v = *(const float4*)(v0p + c0);
    const float4 a0v = *(const float4*)(a0p + c0);
    const float* w0a = &w0v.x; const float* v0a = &v0v.x; const float* a0a = &a0v.x;

    float4 kraw[2];
    kraw[0] = *(const float4*)(g_k + row1 * C_ + c0);
    kraw[1] = *(const float4*)(g_k + (row1 + 1) * C_ + c0);
    float np0 = fmaf(kraw[0].x, kraw[0].x, kraw[0].y * kraw[0].y)
              + fmaf(kraw[0].z, kraw[0].z, kraw[0].w * kraw[0].w);
    float np1 = fmaf(kraw[1].x, kraw[1].x, kraw[1].y * kraw[1].y)
              + fmaf(kraw[1].z, kraw[1].z, kraw[1].w * kraw[1].w);
#pragma unroll
    for (int off = 8; off; off >>= 1) {
        np0 += __shfl_xor_sync(0xffffffffu, np0, off);
        np1 += __shfl_xor_sync(0xffffffffu, np1, off);
    }
    float inv[2];
    inv[0] = 1.f / fmaxf(sqrtf(np0), 1e-12f);
    inv[1] = 1.f / fmaxf(sqrtf(np1), 1e-12f);

    float ews[2][4], vns[2][4], qs[2][4], ks[2][4], as_[2][4], bs[2][4];

#pragma unroll
    for (int r = 0; r < 2; r++) {
        const size_t row   = row1 + r;
        const size_t base  = row * C_ + c0;
        const size_t dbase = row * (4 * C_) + c0;
        float4 wdel = *(const float4*)(g_deltas + dbase);
        float4 vdel = *(const float4*)(g_deltas + dbase + 1024);
        float4 adel = *(const float4*)(g_deltas + dbase + 2048);
        float4 gdel = *(const float4*)(g_deltas + dbase + 3072);
        float4 vraw = *(const float4*)(g_v  + base);
        float4 vfr  = *(const float4*)(g_vf + base);
        float4 qraw = *(const float4*)(g_q  + base);
        const float* wd = &wdel.x; const float* vd = &vdel.x;
        const float* ad = &adel.x; const float* gd = &gdel.x;
        const float* kr = &kraw[r].x; const float* vr = &vraw.x;
        const float* vf = &vfr.x;  const float* qr = &qraw.x;

        float gs[4];
#pragma unroll
        for (int u = 0; u < 4; u++) {
            float xx = -(w0a[u] + wd[u]);
            float sp = (xx > 20.f) ? xx : log1pf(expf(xx));
            float logw = -expf(-sp - 0.5f);
            ews[r][u] = expf(__bfloat162float(__float2bfloat16(logw)));

            float sv = 1.f / (1.f + expf(-(v0a[u] + vd[u])));
            float vnew = vr[u] + (vf[u] - vr[u]) * sv;
            vns[r][u] = __bfloat162float(__float2bfloat16(vnew));

            float a = 1.f / (1.f + expf(-(a0a[u] + ad[u])));
            gs[u] = 1.f + gd[u];

            float kk = kr[u] * inv[r];
            ks[r][u]  = __bfloat162float(__float2bfloat16(kr[u] * a));
            as_[r][u] = __bfloat162float(__float2bfloat16(-kk));
            bs[r][u]  = __bfloat162float(__float2bfloat16(kk * a));
            qs[r][u]  = __bfloat162float(__float2bfloat16(qr[u]));
        }
        *(float4*)(g_gate + base) = make_float4(gs[0], gs[1], gs[2], gs[3]);
        __nv_bfloat162 v01 = __floats2bfloat162_rn(vns[r][0], vns[r][1]);
        __nv_bfloat162 v23 = __floats2bfloat162_rn(vns[r][2], vns[r][3]);
        uint2 vp;
        vp.x = *(const unsigned int*)&v01;
        vp.y = *(const unsigned int*)&v23;
        *(uint2*)(g_sv + base) = vp;
    }

    float rbq1 = 0.f, rkq1 = 0.f, rbq2 = 0.f, rkq2 = 0.f;
#pragma unroll
    for (int u = 0; u < 4; u++) {
        rbq1 = fmaf(qs[0][u], bs[0][u], rbq1);
        rkq1 = fmaf(qs[0][u], ks[0][u], rkq1);
        rbq2 = fmaf(qs[1][u], bs[1][u], rbq2);
        rkq2 = fmaf(qs[1][u], ks[1][u], rkq2);
    }
#pragma unroll
    for (int off = 8; off; off >>= 1) {
        rbq1 += __shfl_xor_sync(0xffffffffu, rbq1, off);
        rkq1 += __shfl_xor_sync(0xffffffffu, rkq1, off);
        rbq2 += __shfl_xor_sync(0xffffffffu, rbq2, off);
        rkq2 += __shfl_xor_sync(0xffffffffu, rkq2, off);
    }

    float qt[4];
#pragma unroll
    for (int u = 0; u < 4; u++)
        qt[u] = fmaf(ews[1][u], qs[1][u], as_[1][u] * rbq2);

    float c1 = 0.f, c2 = 0.f, sc1 = 0.f, sc2 = 0.f;
#pragma unroll
    for (int u = 0; u < 4; u++) {
        c1  = fmaf(bs[0][u], as_[1][u], c1);
        c2  = fmaf(ks[0][u], as_[1][u], c2);
        sc1 = fmaf(bs[0][u], qt[u],  sc1);
        sc2 = fmaf(ks[0][u], qt[u],  sc2);
    }
#pragma unroll
    for (int off = 8; off; off >>= 1) {
        c1  += __shfl_xor_sync(0xffffffffu, c1,  off);
        c2  += __shfl_xor_sync(0xffffffffu, c2,  off);
        sc1 += __shfl_xor_sync(0xffffffffu, sc1, off);
        sc2 += __shfl_xor_sync(0xffffffffu, sc2, off);
    }

    float4 dd, aa, qw, qtv, v1, v3;
    float* ddp = &dd.x; float* aap = &aa.x; float* qwp = &qw.x;
    float* qtp = &qtv.x; float* v1p = &v1.x; float* v3p = &v3.x;
#pragma unroll
    for (int u = 0; u < 4; u++) {
        ddp[u] = ews[0][u] * ews[1][u];
        aap[u] = ews[0][u] * as_[1][u];
        qwp[u] = ews[0][u] * qs[0][u];
        qtp[u] = ews[0][u] * qt[u];
        v1p[u] = fmaf(bs[0][u], ews[1][u], c1 * bs[1][u]);
        v3p[u] = fmaf(ks[0][u], ews[1][u], c2 * bs[1][u]);
    }

    __nv_bfloat162 a01 = __floats2bfloat162_rn(as_[0][0], as_[0][1]);
    __nv_bfloat162 a23 = __floats2bfloat162_rn(as_[0][2], as_[0][3]);
    __nv_bfloat162 b01 = __floats2bfloat162_rn(bs[1][0], bs[1][1]);
    __nv_bfloat162 b23 = __floats2bfloat162_rn(bs[1][2], bs[1][3]);
    __nv_bfloat162 k01 = __floats2bfloat162_rn(ks[1][0], ks[1][1]);
    __nv_bfloat162 k23 = __floats2bfloat162_rn(ks[1][2], ks[1][3]);
    __nv_bfloat162 s101 = __floats2bfloat162_rn(vns[0][0], vns[0][1]);
    __nv_bfloat162 s123 = __floats2bfloat162_rn(vns[0][2], vns[0][3]);
    __nv_bfloat162 s201 = __floats2bfloat162_rn(vns[1][0], vns[1][1]);
    __nv_bfloat162 s223 = __floats2bfloat162_rn(vns[1][2], vns[1][3]);

    char* gp = g_pack + ((size_t)prow * H_ + h) * PACKB_;
    *(float4*)(gp + 0    + 16 * li) = dd;
    *(float4*)(gp + 256  + 16 * li) = aa;
    *(float4*)(gp + 512  + 16 * li) = qw;
    *(float4*)(gp + 768  + 16 * li) = qtv;
    *(float4*)(gp + 1024 + 16 * li) = v1;
    *(float4*)(gp + 1280 + 16 * li) = v3;
    *(uint2*)(gp + 1536 + 8 * li) = make_uint2(*(const unsigned int*)&a01,
                                               *(const unsigned int*)&a23);
    *(uint2*)(gp + 1664 + 8 * li) = make_uint2(*(const unsigned int*)&b01,
                                               *(const unsigned int*)&b23);
    *(uint2*)(gp + 1792 + 8 * li) = make_uint2(*(const unsigned int*)&k01,
                                               *(const unsigned int*)&k23);
    *(uint2*)(gp + 1952 + 8 * li) = make_uint2(*(const unsigned int*)&s101,
                                               *(const unsigned int*)&s123);
    *(uint2*)(gp + 2080 + 8 * li) = make_uint2(*(const unsigned int*)&s201,
                                               *(const unsigned int*)&s223);
    if (li == 0) {
        *(float4*)(gp + 1920) = make_float4(rbq1, rkq1, sc1, sc2);
        *(float*)(gp + 1936)  = rkq2;
    }
}

// ---------------- kernel 4: pair-fused scan (R13: single chain, 512 warps) --
#define SRING_ 8
#define SCAN_SMEM (2 * SRING_ * PACKB_)   // 40960 B

__global__ __launch_bounds__(64)
void scan_kernel()
{
    extern __shared__ char ssm[];
    const int bh = blockIdx.x;
    const int b = bh >> 4, h = bh & 15;
    const int wid  = threadIdx.x >> 5;
    const int lane = threadIdx.x & 31;
    const int quarter = lane >> 3;
    const int li2  = lane & 7;
    const int vrow = blockIdx.y * 8 + wid * 4 + quarter;

    const size_t packbh = ((size_t)(b * NP_) * H_ + h) * PACKB_;
    const size_t yb     = (size_t)b * T_ * C_ + h * 64 + vrow;
    const uint32_t ring = smem_u32(ssm) + (uint32_t)wid * (SRING_ * PACKB_);

    auto issue_pair = [&](int p) {
        const char* src = g_pack + packbh + (size_t)p * PSTR_ + lane * 16;
        const uint32_t dst = ring + (uint32_t)(p & (SRING_ - 1)) * PACKB_ + lane * 16;
#pragma unroll
        for (int c = 0; c < 5; c++)
            CPA16(dst + c * 512, src + c * 512);
    };

#pragma unroll
    for (int p = 0; p < 7; p++) { issue_pair(p); CPA_COMMIT(); }

    float s[8];
#pragma unroll
    for (int i = 0; i < 8; i++) s[i] = 0.f;

    const uint32_t oA  = li2 * 32;
    const uint32_t oU  = li2 * 16;

    CPA_WAIT(6);
    __syncwarp();
    uint4  Ppa;
    float4 Paa0, Paa1, Pqw0, Pqw1, Pqt0, Pqt1;
    {
        const uint32_t st0 = ring;
        Ppa  = lds128u(st0 + 1536 + oU);
        Paa0 = lds128f(st0 + 256 + oA); Paa1 = lds128f(st0 + 256 + oA + 16);
        Pqw0 = lds128f(st0 + 512 + oA); Pqw1 = lds128f(st0 + 512 + oA + 16);
        Pqt0 = lds128f(st0 + 768 + oA); Pqt1 = lds128f(st0 + 768 + oA + 16);
    }

    for (int p = 0; p < NP_; p++) {
        const uint32_t st = ring + (uint32_t)(p & (SRING_ - 1)) * PACKB_;

        const uint4  paU = Ppa;
        const float4 aa0 = Paa0, aa1 = Paa1;
        const float4 qw0 = Pqw0, qw1 = Pqw1;
        const float4 qt0 = Pqt0, qt1 = Pqt1;

        CPA_WAIT(5);
        __syncwarp();
        {
            int pf = p + 1; if (pf > NP_ - 1) pf = NP_ - 1;
            const uint32_t stn = ring + (uint32_t)(pf & (SRING_ - 1)) * PACKB_;
            Ppa  = lds128u(stn + 1536 + oU);
            Paa0 = lds128f(stn + 256 + oA); Paa1 = lds128f(stn + 256 + oA + 16);
            Pqw0 = lds128f(stn + 512 + oA); Pqw1 = lds128f(stn + 512 + oA + 16);
            Pqt0 = lds128f(stn + 768 + oA); Pqt1 = lds128f(stn + 768 + oA + 16);
        }

        {
            int pn = p + 7;
            if (pn < NP_) issue_pair(pn);
            CPA_COMMIT();
        }

        const float vv1 = ldsbf16(st + 1952 + vrow * 2);
        const float vv2 = ldsbf16(st + 2080 + vrow * 2);
        const uint4 pbU = lds128u(st + 1664 + oU);
        const uint4 pkU = lds128u(st + 1792 + oU);
        const float4 dd0 = lds128f(st + 0 + oA),    dd1 = lds128f(st + 0 + oA + 16);
        const float4 v10 = lds128f(st + 1024 + oA), v11 = lds128f(st + 1024 + oA + 16);
        const float4 v30 = lds128f(st + 1280 + oA), v31 = lds128f(st + 1280 + oA + 16);
        const float4 sc4 = lds128f(st + 1920);
        const float rkq2 = ldsf32(st + 1936);

        float2 a01 = bf2(paU.x), a23 = bf2(paU.y), a45 = bf2(paU.z), a67 = bf2(paU.w);
        float r1 = ((s[0]*a01.x + s[1]*a01.y) + (s[2]*a23.x + s[3]*a23.y))
                 + ((s[4]*a45.x + s[5]*a45.y) + (s[6]*a67.x + s[7]*a67.y));
        float r2 = ((s[0]*aa0.x + s[1]*aa0.y) + (s[2]*aa0.z + s[3]*aa0.w))
                 + ((s[4]*aa1.x + s[5]*aa1.y) + (s[6]*aa1.z + s[7]*aa1.w));
        float r3 = ((s[0]*qw0.x + s[1]*qw0.y) + (s[2]*qw0.z + s[3]*qw0.w))
                 + ((s[4]*qw1.x + s[5]*qw1.y) + (s[6]*qw1.z + s[7]*qw1.w));
        float r4 = ((s[0]*qt0.x + s[1]*qt0.y) + (s[2]*qt0.z + s[3]*qt0.w))
                 + ((s[4]*qt1.x + s[5]*qt1.y) + (s[6]*qt1.z + s[7]*qt1.w));

#pragma unroll
        for (int off = 4; off; off >>= 1) {
            r1 += __shfl_xor_sync(0xffffffffu, r1, off);
            r2 += __shfl_xor_sync(0xffffffffu, r2, off);
            r3 += __shfl_xor_sync(0xffffffffu, r3, off);
            r4 += __shfl_xor_sync(0xffffffffu, r4, off);
        }

        float2 b01 = bf2(pbU.x), b23 = bf2(pbU.y), b45 = bf2(pbU.z), b67 = bf2(pbU.w);
        float2 k01 = bf2(pkU.x), k23 = bf2(pkU.y), k45 = bf2(pkU.z), k67 = bf2(pkU.w);

        s[0] = s[0]*dd0.x + r1*v10.x + r2*b01.x + vv1*v30.x + vv2*k01.x;
        s[1] = s[1]*dd0.y + r1*v10.y + r2*b01.y + vv1*v30.y + vv2*k01.y;
        s[2] = s[2]*dd0.z + r1*v10.z + r2*b23.x + vv1*v30.z + vv2*k23.x;
        s[3] = s[3]*dd0.w + r1*v10.w + r2*b23.y + vv1*v30.w + vv2*k23.y;
        s[4] = s[4]*dd1.x + r1*v11.x + r2*b45.x + vv1*v31.x + vv2*k45.x;
        s[5] = s[5]*dd1.y + r1*v11.y + r2*b45.y + vv1*v31.y + vv2*k45.y;
        s[6] = s[6]*dd1.z + r1*v11.z + r2*b67.x + vv1*v31.z + vv2*k67.x;
        s[7] = s[7]*dd1.w + r1*v11.w + r2*b67.y + vv1*v31.w + vv2*k67.y;

        if (li2 == 0) {
            g_yscan[yb + (size_t)(2 * p)     * C_] =
                fmaf(r1, sc4.x, fmaf(vv1, sc4.y, r3));
            g_yscan[yb + (size_t)(2 * p + 1) * C_] =
                fmaf(r1, sc4.z, fmaf(vv1, sc4.w, fmaf(vv2, rkq2, r4)));
        }
    }
}

// ---------------- kernel 5: y corrections (emit bf16 hi/lo) ----------------
__global__ void ycorr_kernel(const float* __restrict__ x,
                             const float* __restrict__ r_k)
{
    const int gh   = blockIdx.x * 8 + (threadIdx.x >> 5);
    const int lane = threadIdx.x & 31;
    const int i = gh >> 4, h = gh & 15;
    const size_t base = (size_t)i * C_ + h * 64 + lane * 2;

    float x0v = x[base], x1v = x[base + 1];
    float v0v = __bfloat162float(g_sv[base]);
    float v1v = __bfloat162float(g_sv[base + 1]);

    float xs = x0v * x0v + x1v * x1v;
    float vs = v0v * v0v + v1v * v1v;
#pragma unroll
    for (int off = 16; off; off >>= 1) {
        xs += __shfl_xor_sync(0xffffffffu, xs, off);
        vs += __shfl_xor_sync(0xffffffffu, vs, off);
    }
    float xnorm = sqrtf(xs);
    float vnorm = sqrtf(vs);
    float un = 1.f - xnorm / (vnorm + 1e-12f);

    float rk0 = r_k[h * 64 + lane * 2];
    float rk1 = r_k[h * 64 + lane * 2 + 1];
    float u0 = un / (1.f + expf(-rk0));
    float u1 = un / (1.f + expf(-rk1));

    const float scale = 0.125f;
    float y0 = (g_yscan[base]     * scale + v0v * u0) * g_gate[base];
    float y1 = (g_yscan[base + 1] * scale + v1v * u1) * g_gate[base + 1];
    f2hl(y0, g_yfh[base],     g_yfl[base]);
    f2hl(y1, g_yfh[base + 1], g_yfl[base + 1]);
}

// ---------------- launch ----------------------------------------------------
extern "C" void kernel_launch(void* const* d_in, const int* in_sizes, int n_in,
                              void* d_out, int out_size)
{
    const float* residual = (const float*)d_in[0];
    const float* x        = (const float*)d_in[1];
    const float* x0       = (const float*)d_in[2];
    const float* dx0      = (const float*)d_in[3];
    const float* Wq       = (const float*)d_in[4];
    const float* Wk       = (const float*)d_in[5];
    const float* Wv       = (const float*)d_in[6];
    const float* Wproj    = (const float*)d_in[7];
    const float* x_q      = (const float*)d_in[8];
    const float* x_k      = (const float*)d_in[9];
    const float* x_v      = (const float*)d_in[10];
    const float* v0       = (const float*)d_in[11];
    const float* w0       = (const float*)d_in[12];
    const float* a0       = (const float*)d_in[13];
    const float* miss     = (const float*)d_in[14];
    const float* r_k      = (const float*)d_in[15];
    float* out = (float*)d_out;

    __nv_bfloat16 *xqh, *xql, *xkh, *xkl, *xvh, *xvl, *x0h, *x0l;
    __nv_bfloat16 *wqh, *wql, *wkh, *wkl, *wvh, *wvl, *wph, *wpl;
    __nv_bfloat16 *xh, *xl, *mth, *mtl, *yfh, *yfl;
    float *pq, *pk, *pv, *pvf, *pdel;
    cudaGetSymbolAddress((void**)&xqh, g_xqh); cudaGetSymbolAddress((void**)&xql, g_xql);
    cudaGetSymbolAddress((void**)&xkh, g_xkh); cudaGetSymbolAddress((void**)&xkl, g_xkl);
    cudaGetSymbolAddress((void**)&xvh, g_xvh); cudaGetSymbolAddress((void**)&xvl, g_xvl);
    cudaGetSymbolAddress((void**)&x0h, g_x0h); cudaGetSymbolAddress((void**)&x0l, g_x0l);
    cudaGetSymbolAddress((void**)&wqh, g_wqh); cudaGetSymbolAddress((void**)&wql, g_wql);
    cudaGetSymbolAddress((void**)&wkh, g_wkh); cudaGetSymbolAddress((void**)&wkl, g_wkl);
    cudaGetSymbolAddress((void**)&wvh, g_wvh); cudaGetSymbolAddress((void**)&wvl, g_wvl);
    cudaGetSymbolAddress((void**)&wph, g_wph); cudaGetSymbolAddress((void**)&wpl, g_wpl);
    cudaGetSymbolAddress((void**)&xh,  g_xh);  cudaGetSymbolAddress((void**)&xl,  g_xl);
    cudaGetSymbolAddress((void**)&mth, g_mth); cudaGetSymbolAddress((void**)&mtl, g_mtl);
    cudaGetSymbolAddress((void**)&yfh, g_yfh); cudaGetSymbolAddress((void**)&yfl, g_yfl);
    cudaGetSymbolAddress((void**)&pq,  g_q);   cudaGetSymbolAddress((void**)&pk,  g_k);
    cudaGetSymbolAddress((void**)&pv,  g_v);   cudaGetSymbolAddress((void**)&pvf, g_vf);
    cudaGetSymbolAddress((void**)&pdel, g_deltas);

    cudaFuncSetAttribute(gemm_mma4, cudaFuncAttributeMaxDynamicSharedMemorySize, GSMEM_BYTES);
    cudaFuncSetAttribute(gemm_mma<false>, cudaFuncAttributeMaxDynamicSharedMemorySize, GSMEM_BYTES);
    cudaFuncSetAttribute(gemm_mma<true>,  cudaFuncAttributeMaxDynamicSharedMemorySize, GSMEM_BYTES);
    cudaFuncSetAttribute(scan_kernel, cudaFuncAttributeMaxDynamicSharedMemorySize, SCAN_SMEM);

    // conversions (independent)
    conv_w4<<<4 * C_ * C_ / 256, 256>>>(Wq, Wk, Wv, Wproj);
    conv_xmt<<<2 * ROWS_ * 128 / 256, 256>>>(x, miss);
    prep_kernel<<<ELEMS_ / 256, 256>>>(x, x0, dx0, x_q, x_k, x_v);

    // fused projections: [4096,1024] = A @ W^T, K=1024, 4 operand sets
    G4 g4;
    g4.ah[0] = xqh; g4.al[0] = xql; g4.bh[0] = wqh; g4.bl[0] = wql; g4.out[0] = pq;
    g4.ah[1] = xkh; g4.al[1] = xkl; g4.bh[1] = wkh; g4.bl[1] = wkl; g4.out[1] = pk;
    g4.ah[2] = xvh; g4.al[2] = xvl; g4.bh[2] = wvh; g4.bl[2] = wvl; g4.out[2] = pv;
    g4.ah[3] = x0h; g4.al[3] = x0l; g4.bh[3] = wvh; g4.bl[3] = wvl; g4.out[3] = pvf;
    gemm_mma4<<<dim3(C_ / 64, ROWS_ / 128, 4), 256, GSMEM_BYTES>>>(g4, C_, C_);

    // deltas: [4096,4096] = x[:, :128] @ missT^T, K=128
    dim3 gD(4 * C_ / 64, ROWS_ / 128);
    gemm_mma<false><<<gD, 256, GSMEM_BYTES>>>(xh, xl, mth, mtl, nullptr, pdel, 4 * C_, 128);

    // fused post ops + pair fusion → packed operand blocks
    postpair_kernel<<<NPROW_ * 8 / 8, 256>>>(w0, v0, a0);

    // pair-fused scan (R13 proven config: 256 blocks x 2 warps, 4 rows/warp)
    scan_kernel<<<dim3(B_ * H_, 8), 64, SCAN_SMEM>>>();

    // corrections + gate (emits yfin hi/lo)
    ycorr_kernel<<<ROWS_ * H_ / 8, 256>>>(x, r_k);

    // out = residual + yfin @ Wproj^T
    gemm_mma<true><<<dim3(C_ / 64, ROWS_ / 128), 256, GSMEM_BYTES>>>(
        yfh, yfl, wph, wpl, residual, out, C_, C_);
}